// round 6
// baseline (speedup 1.0000x reference)
#include <cuda_runtime.h>
#include <cstdint>

// Embedding gather via bulk-async copy engine:
//   out[token, :] = embedding[input_ids[token], :]
// input_ids: [4096] i32, embedding: [32000,1024] f32, out: [4096,1024] f32.
//
// Each CTA (32 threads) handles ROWS_PER_CTA=8 rows of 4096 B each, staged
// through smem with cp.async.bulk (HW copy engine — in-flight bytes are held
// by the async queues, not registers, so DRAM latency is hidden regardless
// of ptxas scheduling). Lanes 0-7: one row each.
//   1. lane r loads id -> issues cp.async.bulk G->S against shared mbarrier
//   2. single wait (expect_tx = 8*4096 bytes)
//   3. lane r issues cp.async.bulk S->G, commit, wait_group
// 512 CTAs, ~3.5/SM resident, ~112 KB in flight per SM.

static constexpr int ROW_BYTES    = 4096;   // 1024 f32
static constexpr int ROWS_PER_CTA = 8;
static constexpr int STAGE_BYTES  = ROWS_PER_CTA * ROW_BYTES;  // 32 KB

__device__ __forceinline__ uint32_t smem_u32(const void* p) {
    uint32_t a;
    asm("{ .reg .u64 t; cvta.to.shared.u64 t, %1; cvt.u32.u64 %0, t; }"
        : "=r"(a) : "l"(p));
    return a;
}

__global__ void __launch_bounds__(32)
embed_gather_bulk(const int* __restrict__ ids,
                  const char* __restrict__ emb,
                  char* __restrict__ out,
                  int n_tokens)
{
    __shared__ alignas(128) char buf[STAGE_BYTES];
    __shared__ alignas(8)  uint64_t mbar;

    const int lane = threadIdx.x;
    const int base = blockIdx.x * ROWS_PER_CTA;

    const uint32_t mbar_a = smem_u32(&mbar);
    const uint32_t buf_a  = smem_u32(buf);

    // --- init barrier + fence to async proxy ---
    if (lane == 0) {
        asm volatile("mbarrier.init.shared.b64 [%0], 1;" :: "r"(mbar_a) : "memory");
        asm volatile("fence.proxy.async.shared::cta;" ::: "memory");
        asm volatile("mbarrier.arrive.expect_tx.shared.b64 _, [%0], %1;"
                     :: "r"(mbar_a), "r"((uint32_t)STAGE_BYTES) : "memory");
    }
    __syncwarp();

    // --- lanes 0-7: issue bulk loads G->S (one 4 KB row each) ---
    if (lane < ROWS_PER_CTA) {
        int token = base + lane;
        int id = (token < n_tokens) ? ids[token] : 0;
        const char* src = emb + (size_t)id * ROW_BYTES;
        uint32_t dst = buf_a + lane * ROW_BYTES;
        asm volatile(
            "cp.async.bulk.shared::cta.global.mbarrier::complete_tx::bytes "
            "[%0], [%1], %2, [%3];"
            :: "r"(dst), "l"(src), "r"((uint32_t)ROW_BYTES), "r"(mbar_a)
            : "memory");
    }

    // --- wait for all 8 rows (parity 0; barrier is re-inited every launch) ---
    {
        uint32_t done;
        asm volatile(
            "{\n\t"
            ".reg .pred p;\n\t"
            "mbarrier.try_wait.parity.shared.b64 p, [%1], 0;\n\t"
            "selp.b32 %0, 1, 0, p;\n\t"
            "}"
            : "=r"(done) : "r"(mbar_a) : "memory");
        if (!done) {
            asm volatile(
                "{\n\t"
                ".reg .pred P1;\n\t"
                "WL_%=:\n\t"
                "mbarrier.try_wait.parity.shared.b64 P1, [%0], 0, 0x989680;\n\t"
                "@P1 bra.uni WD_%=;\n\t"
                "bra.uni WL_%=;\n\t"
                "WD_%=:\n\t"
                "}"
                :: "r"(mbar_a) : "memory");
        }
    }

    // --- lanes 0-7: issue bulk stores S->G ---
    if (lane < ROWS_PER_CTA) {
        int token = base + lane;
        if (token < n_tokens) {
            char* dst = out + (size_t)token * ROW_BYTES;
            uint32_t src = buf_a + lane * ROW_BYTES;
            asm volatile(
                "cp.async.bulk.global.shared::cta.bulk_group [%0], [%1], %2;"
                :: "l"(dst), "r"(src), "r"((uint32_t)ROW_BYTES)
                : "memory");
            asm volatile("cp.async.bulk.commit_group;" ::: "memory");
            asm volatile("cp.async.bulk.wait_group.read 0;" ::: "memory");
        }
    }
}

extern "C" void kernel_launch(void* const* d_in, const int* in_sizes, int n_in,
                              void* d_out, int out_size)
{
    const int*  ids = (const int*)d_in[0];
    const char* emb = (const char*)d_in[1];
    char*       out = (char*)d_out;

    int n_tokens = in_sizes[0];   // 4096
    int grid = (n_tokens + ROWS_PER_CTA - 1) / ROWS_PER_CTA;  // 512
    embed_gather_bulk<<<grid, 32>>>(ids, emb, out, n_tokens);
}